// round 1
// baseline (speedup 1.0000x reference)
#include <cuda_runtime.h>

// Problem constants (match reference)
#define N_DATA    500000
#define FEAT_DIM  512
#define NUM_CLASS 10000
#define BATCH     8192
#define MOMENTUM  0.9f

#define LAT_ELEMS   ((long long)N_DATA * FEAT_DIM)      // 256,000,000
#define CS_ELEMS    ((long long)NUM_CLASS * FEAT_DIM)   //   5,120,000

// ---------------------------------------------------------------------------
// Kernel 1: bulk copy lat_memory -> out[0:LAT], class_sums -> out[LAT:LAT+CS]
// Pure streaming, float4 vectorized, grid-stride.
// ---------------------------------------------------------------------------
__global__ void copy_kernel(const float4* __restrict__ lat,
                            const float4* __restrict__ cs,
                            float4* __restrict__ out_lat,
                            float4* __restrict__ out_cs)
{
    const long long n_lat4 = LAT_ELEMS / 4;   // 64,000,000
    const long long n_cs4  = CS_ELEMS / 4;    //  1,280,000
    const long long total  = n_lat4 + n_cs4;

    long long stride = (long long)gridDim.x * blockDim.x;
    for (long long i = (long long)blockIdx.x * blockDim.x + threadIdx.x;
         i < total; i += stride) {
        if (i < n_lat4) {
            out_lat[i] = lat[i];
        } else {
            long long j = i - n_lat4;
            out_cs[j] = cs[j];
        }
    }
}

// ---------------------------------------------------------------------------
// Kernel 2: one block per batch row (8192 blocks, 128 threads).
//   blended = lat[idx]*(1-m) + batch*m ; normalize ; scatter to out_lat[idx]
//   atomicAdd into out_cs[target]
// 512 floats/row = 128 threads * 1 float4 each.
// ---------------------------------------------------------------------------
__global__ __launch_bounds__(128)
void update_kernel(const float*  __restrict__ batch,
                   const float*  __restrict__ lat,
                   const int*    __restrict__ targets,
                   const int*    __restrict__ idx,
                   float* __restrict__ out_lat,
                   float* __restrict__ out_cs)
{
    const int row = blockIdx.x;          // 0..BATCH-1
    const int t   = threadIdx.x;         // 0..127

    const int src_row = idx[row];
    const int cls     = targets[row];

    const float4* lat_row   = (const float4*)(lat   + (long long)src_row * FEAT_DIM);
    const float4* batch_row = (const float4*)(batch + (long long)row     * FEAT_DIM);

    float4 a = lat_row[t];
    float4 b = batch_row[t];

    float4 v;
    v.x = a.x * (1.0f - MOMENTUM) + b.x * MOMENTUM;
    v.y = a.y * (1.0f - MOMENTUM) + b.y * MOMENTUM;
    v.z = a.z * (1.0f - MOMENTUM) + b.z * MOMENTUM;
    v.w = a.w * (1.0f - MOMENTUM) + b.w * MOMENTUM;

    float ss = v.x * v.x + v.y * v.y + v.z * v.z + v.w * v.w;

    // warp reduce
    #pragma unroll
    for (int off = 16; off > 0; off >>= 1)
        ss += __shfl_xor_sync(0xFFFFFFFFu, ss, off);

    // cross-warp reduce (4 warps)
    __shared__ float warp_sums[4];
    const int lane = t & 31, wid = t >> 5;
    if (lane == 0) warp_sums[wid] = ss;
    __syncthreads();
    float total = warp_sums[0] + warp_sums[1] + warp_sums[2] + warp_sums[3];

    float inv_norm = rsqrtf(total);
    // one Newton step for extra precision of rsqrt (cheap, keeps rel_err low)
    inv_norm = inv_norm * (1.5f - 0.5f * total * inv_norm * inv_norm);

    float4 u;
    u.x = v.x * inv_norm;
    u.y = v.y * inv_norm;
    u.z = v.z * inv_norm;
    u.w = v.w * inv_norm;

    // scatter normalized row into output lat memory
    float4* out_row = (float4*)(out_lat + (long long)src_row * FEAT_DIM);
    out_row[t] = u;

    // segment-sum into class_sums region (duplicate targets -> atomics)
    float* cs_row = out_cs + (long long)cls * FEAT_DIM + t * 4;
    atomicAdd(cs_row + 0, u.x);
    atomicAdd(cs_row + 1, u.y);
    atomicAdd(cs_row + 2, u.z);
    atomicAdd(cs_row + 3, u.w);
}

// ---------------------------------------------------------------------------
// Launch
// ---------------------------------------------------------------------------
extern "C" void kernel_launch(void* const* d_in, const int* in_sizes, int n_in,
                              void* d_out, int out_size)
{
    // metadata order: batch_samples, lat_memory, class_sums, targets, idx
    const float* batch = (const float*)d_in[0];
    const float* lat   = (const float*)d_in[1];
    const float* cs    = (const float*)d_in[2];
    const int*   targ  = (const int*)  d_in[3];
    const int*   idx   = (const int*)  d_in[4];

    float* out_lat = (float*)d_out;
    float* out_cs  = out_lat + LAT_ELEMS;

    // Kernel 1: streaming copy. 148 SMs; use a big grid-stride launch.
    {
        const int threads = 256;
        const int blocks  = 148 * 16;   // 2368 CTAs, grid-stride covers 65.28M float4
        copy_kernel<<<blocks, threads>>>((const float4*)lat,
                                         (const float4*)cs,
                                         (float4*)out_lat,
                                         (float4*)out_cs);
    }

    // Kernel 2: blend + normalize + scatter + class segment-sum.
    // Must run after kernel 1 (same stream) so scattered rows win.
    update_kernel<<<BATCH, 128>>>(batch, lat, targ, idx, out_lat, out_cs);
}

// round 2
// speedup vs baseline: 1.0056x; 1.0056x over previous
#include <cuda_runtime.h>

// Problem constants (match reference)
#define N_DATA    500000
#define FEAT_DIM  512
#define NUM_CLASS 10000
#define BATCH     8192
#define MOMENTUM  0.9f

#define LAT_ELEMS   ((long long)N_DATA * FEAT_DIM)      // 256,000,000
#define CS_ELEMS    ((long long)NUM_CLASS * FEAT_DIM)   //   5,120,000

#define ROW_F4      (FEAT_DIM / 4)     // 128 float4 per row
#define COPY_BLOCKS 4096
#define MASK_INT4   (N_DATA / 16)      // 31250 int4 covering the byte mask

// Per-row "this row will be rewritten by the update" flag.
__device__ unsigned char g_mask[N_DATA];

// ---------------------------------------------------------------------------
// Kernel A: clear mask + copy class_sums base into output. Runs first so the
// fused kernel's class atomics cannot race with the base copy.
// ---------------------------------------------------------------------------
__global__ void prep_kernel(const float4* __restrict__ cs,
                            float4* __restrict__ out_cs)
{
    const int n_cs4 = (int)(CS_ELEMS / 4);           // 1,280,000
    const int total = MASK_INT4 + n_cs4;
    int stride = gridDim.x * blockDim.x;
    int4 z = make_int4(0, 0, 0, 0);
    for (int i = blockIdx.x * blockDim.x + threadIdx.x; i < total; i += stride) {
        if (i < MASK_INT4) {
            ((int4*)g_mask)[i] = z;
        } else {
            int j = i - MASK_INT4;
            out_cs[j] = cs[j];
        }
    }
}

// ---------------------------------------------------------------------------
// Kernel B: mark the 8192 rows that the update will rewrite.
// ---------------------------------------------------------------------------
__global__ void set_mask_kernel(const int* __restrict__ idx)
{
    int i = blockIdx.x * blockDim.x + threadIdx.x;
    if (i < BATCH) g_mask[idx[i]] = 1;
}

// ---------------------------------------------------------------------------
// Kernel C (fused): blocks [0, BATCH) do blend+normalize+scatter+class-atomics;
// blocks [BATCH, BATCH+COPY_BLOCKS) stream-copy all non-masked lat rows.
// ---------------------------------------------------------------------------
__global__ __launch_bounds__(128)
void fused_kernel(const float*  __restrict__ batch,
                  const float*  __restrict__ lat,
                  const int*    __restrict__ targets,
                  const int*    __restrict__ idx,
                  float* __restrict__ out_lat,
                  float* __restrict__ out_cs)
{
    const int t = threadIdx.x;   // 0..127

    if (blockIdx.x < BATCH) {
        // ---------------- update path ----------------
        const int row     = blockIdx.x;
        const int src_row = idx[row];
        const int cls     = targets[row];

        const float4* lat_row   = (const float4*)(lat)   + src_row * ROW_F4;
        const float4* batch_row = (const float4*)(batch) + row     * ROW_F4;

        float4 a = lat_row[t];
        float4 b = batch_row[t];

        float4 v;
        v.x = a.x * (1.0f - MOMENTUM) + b.x * MOMENTUM;
        v.y = a.y * (1.0f - MOMENTUM) + b.y * MOMENTUM;
        v.z = a.z * (1.0f - MOMENTUM) + b.z * MOMENTUM;
        v.w = a.w * (1.0f - MOMENTUM) + b.w * MOMENTUM;

        float ss = v.x * v.x + v.y * v.y + v.z * v.z + v.w * v.w;

        #pragma unroll
        for (int off = 16; off > 0; off >>= 1)
            ss += __shfl_xor_sync(0xFFFFFFFFu, ss, off);

        __shared__ float warp_sums[4];
        const int lane = t & 31, wid = t >> 5;
        if (lane == 0) warp_sums[wid] = ss;
        __syncthreads();
        float total = warp_sums[0] + warp_sums[1] + warp_sums[2] + warp_sums[3];

        float inv_norm = rsqrtf(total);
        inv_norm = inv_norm * (1.5f - 0.5f * total * inv_norm * inv_norm);

        float4 u;
        u.x = v.x * inv_norm;
        u.y = v.y * inv_norm;
        u.z = v.z * inv_norm;
        u.w = v.w * inv_norm;

        ((float4*)out_lat)[src_row * ROW_F4 + t] = u;

        float* cs_row = out_cs + (long long)cls * FEAT_DIM + t * 4;
        atomicAdd(cs_row + 0, u.x);
        atomicAdd(cs_row + 1, u.y);
        atomicAdd(cs_row + 2, u.z);
        atomicAdd(cs_row + 3, u.w);
    } else {
        // ---------------- streaming copy path ----------------
        const int cb = blockIdx.x - BATCH;
        const float4* src = (const float4*)lat;
        float4*       dst = (float4*)out_lat;

        for (int r = cb; r < N_DATA; r += 2 * COPY_BLOCKS) {
            int r2 = r + COPY_BLOCKS;
            // issue mask + data loads up front (independent -> MLP)
            unsigned char m1 = g_mask[r];
            float4 v1 = __ldcs(src + r * ROW_F4 + t);
            unsigned char m2 = 0;
            float4 v2;
            if (r2 < N_DATA) {
                m2 = g_mask[r2];
                v2 = __ldcs(src + r2 * ROW_F4 + t);
            }
            if (!m1) __stcs(dst + r * ROW_F4 + t, v1);
            if (r2 < N_DATA && !m2) __stcs(dst + r2 * ROW_F4 + t, v2);
        }
    }
}

// ---------------------------------------------------------------------------
// Launch
// ---------------------------------------------------------------------------
extern "C" void kernel_launch(void* const* d_in, const int* in_sizes, int n_in,
                              void* d_out, int out_size)
{
    // metadata order: batch_samples, lat_memory, class_sums, targets, idx
    const float* batch = (const float*)d_in[0];
    const float* lat   = (const float*)d_in[1];
    const float* cs    = (const float*)d_in[2];
    const int*   targ  = (const int*)  d_in[3];
    const int*   idx   = (const int*)  d_in[4];

    float* out_lat = (float*)d_out;
    float* out_cs  = out_lat + LAT_ELEMS;

    // A: clear mask + copy class_sums base (~41 MB traffic, ~6 us)
    prep_kernel<<<1024, 256>>>((const float4*)cs, (float4*)out_cs);

    // B: mark updated rows
    set_mask_kernel<<<(BATCH + 255) / 256, 256>>>(idx);

    // C: fused update + masked streaming copy
    fused_kernel<<<BATCH + COPY_BLOCKS, 128>>>(batch, lat, targ, idx,
                                               out_lat, out_cs);
}